// round 1
// baseline (speedup 1.0000x reference)
#include <cuda_runtime.h>
#include <math.h>

#define BB 4
#define C 512
#define HS 32
#define H2 64

// ---------------- scratch (no allocations allowed) ----------------
__device__ float g_s0[BB * C];
__device__ float g_s1[BB * C];
__device__ float g_sr[BB * C];
__device__ float g_d0[BB * C];
__device__ float g_d1[BB * C];
__device__ float g_Q[2 * C * C];
__device__ float g_x0[(size_t)BB * C * H2 * H2];   // s0-scaled upsampled maps
__device__ float g_x1[(size_t)BB * C * H2 * H2];   // s1-scaled lrelu(layer0)

__device__ __forceinline__ float conv_scale() {
    // sqrt(2/1.04) / sqrt(512*9)
    return 1.3867504905630728f / 67.88225099390857f;
}
__device__ __forceinline__ float ms_scale() {
    return 0.04419417382415922f;  // sqrt(2/1024)
}
__device__ __forceinline__ float rgb_scale() {
    return 1.3867504905630728f * 0.06231769651245859f;  // _G * sqrt(2/515)
}

// ---------------- styles: s = w @ (ms_w.T * MS) + ms_b -------------
__global__ void styles_kernel(const float* __restrict__ w,
                              const float* __restrict__ ms0_w, const float* __restrict__ ms0_b,
                              const float* __restrict__ ms1_w, const float* __restrict__ ms1_b,
                              const float* __restrict__ msr_w, const float* __restrict__ msr_b)
{
    int gw = (blockIdx.x * blockDim.x + threadIdx.x) >> 5;
    int lane = threadIdx.x & 31;
    if (gw >= 3 * BB * C) return;
    int which = gw / (BB * C);
    int rem = gw % (BB * C);
    int b = rem / C;
    int i = rem % C;
    const float* msw = which == 0 ? ms0_w : which == 1 ? ms1_w : msr_w;
    const float* msb = which == 0 ? ms0_b : which == 1 ? ms1_b : msr_b;
    const float* wr = w + b * C;
    const float* mr = msw + i * C;
    float acc = 0.f;
    for (int j = lane; j < C; j += 32) acc += wr[j] * mr[j];
#pragma unroll
    for (int o = 16; o; o >>= 1) acc += __shfl_xor_sync(0xffffffffu, acc, o);
    if (lane == 0) {
        float s = acc * ms_scale() + msb[i];
        float* dst = which == 0 ? g_s0 : which == 1 ? g_s1 : g_sr;
        dst[b * C + i] = s;
    }
}

// ---------------- Q[co,ci] = sum_t (W*scale)^2 ---------------------
__global__ void q_kernel(const float* __restrict__ w0, const float* __restrict__ w1)
{
    int idx = blockIdx.x * blockDim.x + threadIdx.x;
    if (idx >= 2 * C * C) return;
    const float* W = idx < C * C ? w0 : w1;
    int e = idx < C * C ? idx : idx - C * C;
    const float* p = W + (size_t)e * 9;
    float s = 0.f;
#pragma unroll
    for (int t = 0; t < 9; t++) s += p[t] * p[t];
    float cs = conv_scale();
    g_Q[idx] = s * cs * cs;
}

// ---------------- d[b,co] = rsqrt(sum_ci Q*s^2 + 1e-8) ------------
__global__ void demod_kernel()
{
    int gw = (blockIdx.x * blockDim.x + threadIdx.x) >> 5;
    int lane = threadIdx.x & 31;
    if (gw >= 2 * BB * C) return;
    int layer = gw / (BB * C);
    int rem = gw % (BB * C);
    int b = rem / C;
    int co = rem % C;
    const float* Q = g_Q + (size_t)layer * C * C + (size_t)co * C;
    const float* s = (layer ? g_s1 : g_s0) + b * C;
    float acc = 0.f;
    for (int ci = lane; ci < C; ci += 32) {
        float sv = s[ci];
        acc += Q[ci] * sv * sv;
    }
#pragma unroll
    for (int o = 16; o; o >>= 1) acc += __shfl_xor_sync(0xffffffffu, acc, o);
    if (lane == 0) (layer ? g_d1 : g_d0)[b * C + co] = rsqrtf(acc + 1e-8f);
}

// ---------------- upsample maps 32->64 bilinear, scale by s0 -------
__global__ void upsample_scale_kernel(const float* __restrict__ maps)
{
    int idx = blockIdx.x * blockDim.x + threadIdx.x;
    if (idx >= BB * C * H2 * H2) return;
    int x = idx & 63;
    int y = (idx >> 6) & 63;
    int c = (idx >> 12) & (C - 1);
    int b = idx >> 21;
    float sy = 0.5f * y - 0.25f;
    float sx = 0.5f * x - 0.25f;
    int yi = (int)floorf(sy);
    int xi = (int)floorf(sx);
    float wy = sy - yi;
    float wx = sx - xi;
    int ya = yi < 0 ? 0 : yi;
    int yb = yi + 1 > HS - 1 ? HS - 1 : yi + 1;
    int xa = xi < 0 ? 0 : xi;
    int xb = xi + 1 > HS - 1 ? HS - 1 : xi + 1;
    const float* m = maps + ((size_t)b * C + c) * HS * HS;
    float v = (1.f - wy) * ((1.f - wx) * m[ya * HS + xa] + wx * m[ya * HS + xb]) +
              wy * ((1.f - wx) * m[yb * HS + xa] + wx * m[yb * HS + xb]);
    g_x0[idx] = v * g_s0[b * C + c];
}

// ---------------- 3x3 conv, d-scale + bias + noise + lrelu (+s1) ---
// Block: 64 out-channels x (4 rows x 64 cols). Thread: 8 co x 8 px (px stride 8).
__global__ __launch_bounds__(256)
void conv3x3_kernel(const float* __restrict__ xin, const float* __restrict__ Wg,
                    const float* __restrict__ bias, const float* __restrict__ ns,
                    const float* __restrict__ noise, const float* __restrict__ dmod,
                    const float* __restrict__ snext, float* __restrict__ out,
                    int scale_out)
{
    __shared__ float sX[4 * 6 * 72];   // [ci=4][row=6 (y0-1..y0+4)][col=66 pad 72]
    __shared__ float sW[4 * 9 * 64];   // [ci][tap][co]

    const int tid = threadIdx.x;
    const int cog = tid >> 5;          // 0..7, co sub-block
    const int lane = tid & 31;
    const int tx = lane & 7;           // pixel base within row (stride-8 ownership)
    const int ty = lane >> 3;          // row 0..3
    const int co0 = blockIdx.x * 64;
    const int y0 = blockIdx.y * 4;
    const int b = blockIdx.z;
    const float cs = conv_scale();

    float acc[8][8];
#pragma unroll
    for (int k = 0; k < 8; k++)
#pragma unroll
        for (int j = 0; j < 8; j++) acc[k][j] = 0.f;

    const float* xb = xin + (size_t)b * C * H2 * H2;

#pragma unroll 1
    for (int ci0 = 0; ci0 < C; ci0 += 4) {
        __syncthreads();
        // input tile: 4 ci x 6 rows x 66 cols (zero-padded borders)
        for (int idx = tid; idx < 4 * 6 * 66; idx += 256) {
            int c = idx / 396;
            int rem = idx - c * 396;
            int r = rem / 66;
            int col = rem - r * 66;
            int y = y0 - 1 + r;
            int x = col - 1;
            float v = 0.f;
            if ((unsigned)y < 64u && (unsigned)x < 64u)
                v = xb[(((size_t)(ci0 + c)) * 64 + y) * 64 + x];
            sX[(c * 6 + r) * 72 + col] = v;
        }
        // weights: [ci][tap][co]
        for (int idx = tid; idx < 2304; idx += 256) {
            int co = idx & 63;
            int t = (idx >> 6) % 9;
            int c = idx / 576;
            sW[(c * 9 + t) * 64 + co] =
                Wg[(((size_t)(co0 + co)) * C + (ci0 + c)) * 9 + t] * cs;
        }
        __syncthreads();

#pragma unroll 1
        for (int c = 0; c < 4; c++) {
#pragma unroll
            for (int dy = 0; dy < 3; dy++) {
                const float* xr = &sX[(c * 6 + ty + dy) * 72];
#pragma unroll
                for (int dx = 0; dx < 3; dx++) {
                    const float* wp = &sW[(c * 9 + dy * 3 + dx) * 64 + cog * 8];
                    float wv[8];
#pragma unroll
                    for (int k = 0; k < 8; k++) wv[k] = wp[k];
#pragma unroll
                    for (int j = 0; j < 8; j++) {
                        float xv = xr[tx + 8 * j + dx];
#pragma unroll
                        for (int k = 0; k < 8; k++)
                            acc[k][j] = fmaf(wv[k], xv, acc[k][j]);
                    }
                }
            }
        }
    }

    // epilogue
    const int y = y0 + ty;
    const float* np = noise + ((size_t)b * 64 + y) * 64;
#pragma unroll
    for (int k = 0; k < 8; k++) {
        const int co = co0 + cog * 8 + k;
        const float dv = dmod[b * C + co];
        const float bv = bias[co];
        const float nv = ns[co];
        const float sv = scale_out ? snext[b * C + co] : 1.f;
        float* op = out + (((size_t)b * C + co) * 64 + y) * 64;
#pragma unroll
        for (int j = 0; j < 8; j++) {
            const int x = tx + 8 * j;
            float v = acc[k][j] * dv + bv + nv * np[x];
            v = v >= 0.f ? v : 0.2f * v;
            op[x] = v * sv;
        }
    }
}

// ---------------- to_rgb: rgb_up + 1x1 modulated conv --------------
__global__ void rgb_kernel(const float* __restrict__ rgb_in, const float* __restrict__ rgb_w,
                           const float* __restrict__ rgb_b, const float* __restrict__ h,
                           float* __restrict__ out)
{
    __shared__ float coef[3 * C];
    __shared__ float part[4][3][64];
    int b = blockIdx.x >> 6;
    int y = blockIdx.x & 63;
    int tid = threadIdx.x;
    const float rs = rgb_scale();
    for (int i = tid; i < 3 * C; i += 256) {
        int c2 = i >> 9;
        int co = i & (C - 1);
        coef[i] = rgb_w[c2 * C + co] * rs * g_sr[b * C + co];
    }
    __syncthreads();
    int px = tid & 63;
    int cg = tid >> 6;
    float a0 = 0.f, a1 = 0.f, a2 = 0.f;
    const float* hp = h + (((size_t)b * C + cg * 128) * 64 + y) * 64 + px;
    const float* c0 = coef + cg * 128;
    for (int co = 0; co < 128; co++) {
        float hv = hp[(size_t)co * 4096];
        a0 += c0[co] * hv;
        a1 += c0[C + co] * hv;
        a2 += c0[2 * C + co] * hv;
    }
    part[cg][0][px] = a0;
    part[cg][1][px] = a1;
    part[cg][2][px] = a2;
    __syncthreads();
    if (tid < 192) {
        int c2 = tid / 64;
        int x = tid % 64;
        float s = part[0][c2][x] + part[1][c2][x] + part[2][c2][x] + part[3][c2][x];
        float sy = 0.5f * y - 0.25f;
        float sx = 0.5f * x - 0.25f;
        int yi = (int)floorf(sy);
        int xi = (int)floorf(sx);
        float wy = sy - yi;
        float wx = sx - xi;
        int ya = yi < 0 ? 0 : yi;
        int yb = yi + 1 > HS - 1 ? HS - 1 : yi + 1;
        int xa = xi < 0 ? 0 : xi;
        int xb2 = xi + 1 > HS - 1 ? HS - 1 : xi + 1;
        const float* rp = rgb_in + ((size_t)b * 3 + c2) * HS * HS;
        float up = (1.f - wy) * ((1.f - wx) * rp[ya * HS + xa] + wx * rp[ya * HS + xb2]) +
                   wy * ((1.f - wx) * rp[yb * HS + xa] + wx * rp[yb * HS + xb2]);
        out[(((size_t)b * 3 + c2) * 64 + y) * 64 + x] = up + rgb_b[c2] + s;
    }
}

// ---------------- launch ------------------------------------------
extern "C" void kernel_launch(void* const* d_in, const int* in_sizes, int n_in,
                              void* d_out, int out_size)
{
    const float* maps    = (const float*)d_in[0];
    const float* w       = (const float*)d_in[1];
    const float* rgb     = (const float*)d_in[2];
    const float* noise0  = (const float*)d_in[3];
    const float* noise1  = (const float*)d_in[4];
    const float* conv0_w = (const float*)d_in[5];
    const float* conv0_b = (const float*)d_in[6];
    const float* ms0_w   = (const float*)d_in[7];
    const float* ms0_b   = (const float*)d_in[8];
    const float* ns0     = (const float*)d_in[9];
    const float* conv1_w = (const float*)d_in[10];
    const float* conv1_b = (const float*)d_in[11];
    const float* ms1_w   = (const float*)d_in[12];
    const float* ms1_b   = (const float*)d_in[13];
    const float* ns1     = (const float*)d_in[14];
    const float* rgb_w   = (const float*)d_in[15];
    const float* rgb_b   = (const float*)d_in[16];
    const float* msr_w   = (const float*)d_in[17];
    const float* msr_b   = (const float*)d_in[18];

    float* out = (float*)d_out;
    float* out_rgb = out;                       // (4,3,64,64)
    float* out_h   = out + 4 * 3 * 64 * 64;     // (4,512,64,64)

    float *px0, *px1, *pd0, *pd1, *ps1;
    cudaGetSymbolAddress((void**)&px0, g_x0);
    cudaGetSymbolAddress((void**)&px1, g_x1);
    cudaGetSymbolAddress((void**)&pd0, g_d0);
    cudaGetSymbolAddress((void**)&pd1, g_d1);
    cudaGetSymbolAddress((void**)&ps1, g_s1);

    styles_kernel<<<768, 256>>>(w, ms0_w, ms0_b, ms1_w, ms1_b, msr_w, msr_b);
    q_kernel<<<(2 * C * C + 255) / 256, 256>>>(conv0_w, conv1_w);
    demod_kernel<<<(2 * BB * C * 32 + 255) / 256, 256>>>();
    upsample_scale_kernel<<<(BB * C * H2 * H2) / 256, 256>>>(maps);

    // layer 0: conv(g_x0) -> d0, bias, noise, lrelu, *s1 -> g_x1
    conv3x3_kernel<<<dim3(8, 16, BB), 256>>>(px0, conv0_w, conv0_b, ns0, noise0,
                                             pd0, ps1, px1, 1);
    // layer 1: conv(g_x1) -> d1, bias, noise, lrelu -> out_h
    conv3x3_kernel<<<dim3(8, 16, BB), 256>>>(px1, conv1_w, conv1_b, ns1, noise1,
                                             pd1, nullptr, out_h, 0);

    rgb_kernel<<<BB * 64, 256>>>(rgb, rgb_w, rgb_b, out_h, out_rgb);
}

// round 6
// speedup vs baseline: 1.6131x; 1.6131x over previous
#include <cuda_runtime.h>
#include <math.h>

#define BB 4
#define C 512
#define HS 32
#define H2 64

// ---------------- scratch (no allocations allowed) ----------------
__device__ float g_s0[BB * C];
__device__ float g_s1[BB * C];
__device__ float g_sr[BB * C];
__device__ float g_d0[BB * C];
__device__ float g_d1[BB * C];
__device__ float g_Q[2 * C * C];
__device__ float g_x0[(size_t)BB * C * H2 * H2];   // s0-scaled upsampled maps
__device__ float g_x1[(size_t)BB * C * H2 * H2];   // s1-scaled lrelu(layer0)

__device__ __forceinline__ float conv_scale() {
    // sqrt(2/1.04) / sqrt(512*9)
    return 1.3867504905630728f / 67.88225099390857f;
}
__device__ __forceinline__ float ms_scale() {
    return 0.04419417382415922f;  // sqrt(2/1024)
}
__device__ __forceinline__ float rgb_scale() {
    return 1.3867504905630728f * 0.06231769651245859f;  // _G * sqrt(2/515)
}

// ---------------- styles: s = w @ (ms_w.T * MS) + ms_b -------------
__global__ void styles_kernel(const float* __restrict__ w,
                              const float* __restrict__ ms0_w, const float* __restrict__ ms0_b,
                              const float* __restrict__ ms1_w, const float* __restrict__ ms1_b,
                              const float* __restrict__ msr_w, const float* __restrict__ msr_b)
{
    int gw = (blockIdx.x * blockDim.x + threadIdx.x) >> 5;
    int lane = threadIdx.x & 31;
    if (gw >= 3 * BB * C) return;
    int which = gw / (BB * C);
    int rem = gw % (BB * C);
    int b = rem / C;
    int i = rem % C;
    const float* msw = which == 0 ? ms0_w : which == 1 ? ms1_w : msr_w;
    const float* msb = which == 0 ? ms0_b : which == 1 ? ms1_b : msr_b;
    const float* wr = w + b * C;
    const float* mr = msw + i * C;
    float acc = 0.f;
    for (int j = lane; j < C; j += 32) acc += wr[j] * mr[j];
#pragma unroll
    for (int o = 16; o; o >>= 1) acc += __shfl_xor_sync(0xffffffffu, acc, o);
    if (lane == 0) {
        float s = acc * ms_scale() + msb[i];
        float* dst = which == 0 ? g_s0 : which == 1 ? g_s1 : g_sr;
        dst[b * C + i] = s;
    }
}

// ---------------- Q[co,ci] = sum_t (W*scale)^2 ---------------------
__global__ void q_kernel(const float* __restrict__ w0, const float* __restrict__ w1)
{
    int idx = blockIdx.x * blockDim.x + threadIdx.x;
    if (idx >= 2 * C * C) return;
    const float* W = idx < C * C ? w0 : w1;
    int e = idx < C * C ? idx : idx - C * C;
    const float* p = W + (size_t)e * 9;
    float s = 0.f;
#pragma unroll
    for (int t = 0; t < 9; t++) s += p[t] * p[t];
    float cs = conv_scale();
    g_Q[idx] = s * cs * cs;
}

// ---------------- d[b,co] = rsqrt(sum_ci Q*s^2 + 1e-8) ------------
__global__ void demod_kernel()
{
    int gw = (blockIdx.x * blockDim.x + threadIdx.x) >> 5;
    int lane = threadIdx.x & 31;
    if (gw >= 2 * BB * C) return;
    int layer = gw / (BB * C);
    int rem = gw % (BB * C);
    int b = rem / C;
    int co = rem % C;
    const float* Q = g_Q + (size_t)layer * C * C + (size_t)co * C;
    const float* s = (layer ? g_s1 : g_s0) + b * C;
    float acc = 0.f;
    for (int ci = lane; ci < C; ci += 32) {
        float sv = s[ci];
        acc += Q[ci] * sv * sv;
    }
#pragma unroll
    for (int o = 16; o; o >>= 1) acc += __shfl_xor_sync(0xffffffffu, acc, o);
    if (lane == 0) (layer ? g_d1 : g_d0)[b * C + co] = rsqrtf(acc + 1e-8f);
}

// ---------------- upsample maps 32->64 bilinear, scale by s0 -------
__global__ void upsample_scale_kernel(const float* __restrict__ maps)
{
    int idx = blockIdx.x * blockDim.x + threadIdx.x;
    if (idx >= BB * C * H2 * H2) return;
    int x = idx & 63;
    int y = (idx >> 6) & 63;
    int c = (idx >> 12) & (C - 1);
    int b = idx >> 21;
    float sy = 0.5f * y - 0.25f;
    float sx = 0.5f * x - 0.25f;
    int yi = (int)floorf(sy);
    int xi = (int)floorf(sx);
    float wy = sy - yi;
    float wx = sx - xi;
    int ya = yi < 0 ? 0 : yi;
    int yb = yi + 1 > HS - 1 ? HS - 1 : yi + 1;
    int xa = xi < 0 ? 0 : xi;
    int xb = xi + 1 > HS - 1 ? HS - 1 : xi + 1;
    const float* m = maps + ((size_t)b * C + c) * HS * HS;
    float v = (1.f - wy) * ((1.f - wx) * m[ya * HS + xa] + wx * m[ya * HS + xb]) +
              wy * ((1.f - wx) * m[yb * HS + xa] + wx * m[yb * HS + xb]);
    g_x0[idx] = v * g_s0[b * C + c];
}

// ---------------- 3x3 conv, d-scale + bias + noise + lrelu (+s1) ---
// Block: 64 out-channels x (4 rows x 64 cols). Thread: 8 co x 8 px (px stride 8).
__global__ __launch_bounds__(256)
void conv3x3_kernel(const float* __restrict__ xin, const float* __restrict__ Wg,
                    const float* __restrict__ bias, const float* __restrict__ ns,
                    const float* __restrict__ noise, const float* __restrict__ dmod,
                    const float* __restrict__ snext, float* __restrict__ out,
                    int scale_out)
{
    __shared__ float sX[4 * 6 * 72];   // [ci=4][row=6 (y0-1..y0+4)][col=66 pad 72]
    __shared__ float sW[4 * 9 * 64];   // [ci][tap][co]

    const int tid = threadIdx.x;
    const int cog = tid >> 5;          // 0..7, co sub-block
    const int lane = tid & 31;
    const int tx = lane & 7;           // pixel base within row (stride-8 ownership)
    const int ty = lane >> 3;          // row 0..3
    const int co0 = blockIdx.x * 64;
    const int y0 = blockIdx.y * 4;
    const int b = blockIdx.z;
    const float cs = conv_scale();

    float acc[8][8];
#pragma unroll
    for (int k = 0; k < 8; k++)
#pragma unroll
        for (int j = 0; j < 8; j++) acc[k][j] = 0.f;

    const float* xb = xin + (size_t)b * C * H2 * H2;

#pragma unroll 1
    for (int ci0 = 0; ci0 < C; ci0 += 4) {
        __syncthreads();
        // input tile: 4 ci x 6 rows x 66 cols (zero-padded borders)
        for (int idx = tid; idx < 4 * 6 * 66; idx += 256) {
            int c = idx / 396;
            int rem = idx - c * 396;
            int r = rem / 66;
            int col = rem - r * 66;
            int y = y0 - 1 + r;
            int x = col - 1;
            float v = 0.f;
            if ((unsigned)y < 64u && (unsigned)x < 64u)
                v = xb[(((size_t)(ci0 + c)) * 64 + y) * 64 + x];
            sX[(c * 6 + r) * 72 + col] = v;
        }
        // weights: [ci][tap][co]
        for (int idx = tid; idx < 2304; idx += 256) {
            int co = idx & 63;
            int t = (idx >> 6) % 9;
            int c = idx / 576;
            sW[(c * 9 + t) * 64 + co] =
                Wg[(((size_t)(co0 + co)) * C + (ci0 + c)) * 9 + t] * cs;
        }
        __syncthreads();

#pragma unroll 1
        for (int c = 0; c < 4; c++) {
#pragma unroll
            for (int dy = 0; dy < 3; dy++) {
                const float* xr = &sX[(c * 6 + ty + dy) * 72];
#pragma unroll
                for (int dx = 0; dx < 3; dx++) {
                    const float* wp = &sW[(c * 9 + dy * 3 + dx) * 64 + cog * 8];
                    float wv[8];
#pragma unroll
                    for (int k = 0; k < 8; k++) wv[k] = wp[k];
#pragma unroll
                    for (int j = 0; j < 8; j++) {
                        float xv = xr[tx + 8 * j + dx];
#pragma unroll
                        for (int k = 0; k < 8; k++)
                            acc[k][j] = fmaf(wv[k], xv, acc[k][j]);
                    }
                }
            }
        }
    }

    // epilogue
    const int y = y0 + ty;
    const float* np = noise + ((size_t)b * 64 + y) * 64;
#pragma unroll
    for (int k = 0; k < 8; k++) {
        const int co = co0 + cog * 8 + k;
        const float dv = dmod[b * C + co];
        const float bv = bias[co];
        const float nv = ns[co];
        const float sv = scale_out ? snext[b * C + co] : 1.f;
        float* op = out + (((size_t)b * C + co) * 64 + y) * 64;
#pragma unroll
        for (int j = 0; j < 8; j++) {
            const int x = tx + 8 * j;
            float v = acc[k][j] * dv + bv + nv * np[x];
            v = v >= 0.f ? v : 0.2f * v;
            op[x] = v * sv;
        }
    }
}

// ---------------- to_rgb: rgb_up + 1x1 modulated conv --------------
__global__ void rgb_kernel(const float* __restrict__ rgb_in, const float* __restrict__ rgb_w,
                           const float* __restrict__ rgb_b, const float* __restrict__ h,
                           float* __restrict__ out)
{
    __shared__ float coef[3 * C];
    __shared__ float part[4][3][64];
    int b = blockIdx.x >> 6;
    int y = blockIdx.x & 63;
    int tid = threadIdx.x;
    const float rs = rgb_scale();
    for (int i = tid; i < 3 * C; i += 256) {
        int c2 = i >> 9;
        int co = i & (C - 1);
        coef[i] = rgb_w[c2 * C + co] * rs * g_sr[b * C + co];
    }
    __syncthreads();
    int px = tid & 63;
    int cg = tid >> 6;
    float a0 = 0.f, a1 = 0.f, a2 = 0.f;
    const float* hp = h + (((size_t)b * C + cg * 128) * 64 + y) * 64 + px;
    const float* c0 = coef + cg * 128;
    for (int co = 0; co < 128; co++) {
        float hv = hp[(size_t)co * 4096];
        a0 += c0[co] * hv;
        a1 += c0[C + co] * hv;
        a2 += c0[2 * C + co] * hv;
    }
    part[cg][0][px] = a0;
    part[cg][1][px] = a1;
    part[cg][2][px] = a2;
    __syncthreads();
    if (tid < 192) {
        int c2 = tid / 64;
        int x = tid % 64;
        float s = part[0][c2][x] + part[1][c2][x] + part[2][c2][x] + part[3][c2][x];
        float sy = 0.5f * y - 0.25f;
        float sx = 0.5f * x - 0.25f;
        int yi = (int)floorf(sy);
        int xi = (int)floorf(sx);
        float wy = sy - yi;
        float wx = sx - xi;
        int ya = yi < 0 ? 0 : yi;
        int yb = yi + 1 > HS - 1 ? HS - 1 : yi + 1;
        int xa = xi < 0 ? 0 : xi;
        int xb2 = xi + 1 > HS - 1 ? HS - 1 : xi + 1;
        const float* rp = rgb_in + ((size_t)b * 3 + c2) * HS * HS;
        float up = (1.f - wy) * ((1.f - wx) * rp[ya * HS + xa] + wx * rp[ya * HS + xb2]) +
                   wy * ((1.f - wx) * rp[yb * HS + xa] + wx * rp[yb * HS + xb2]);
        out[(((size_t)b * 3 + c2) * 64 + y) * 64 + x] = up + rgb_b[c2] + s;
    }
}

// ---------------- launch ------------------------------------------
extern "C" void kernel_launch(void* const* d_in, const int* in_sizes, int n_in,
                              void* d_out, int out_size)
{
    const float* maps    = (const float*)d_in[0];
    const float* w       = (const float*)d_in[1];
    const float* rgb     = (const float*)d_in[2];
    const float* noise0  = (const float*)d_in[3];
    const float* noise1  = (const float*)d_in[4];
    const float* conv0_w = (const float*)d_in[5];
    const float* conv0_b = (const float*)d_in[6];
    const float* ms0_w   = (const float*)d_in[7];
    const float* ms0_b   = (const float*)d_in[8];
    const float* ns0     = (const float*)d_in[9];
    const float* conv1_w = (const float*)d_in[10];
    const float* conv1_b = (const float*)d_in[11];
    const float* ms1_w   = (const float*)d_in[12];
    const float* ms1_b   = (const float*)d_in[13];
    const float* ns1     = (const float*)d_in[14];
    const float* rgb_w   = (const float*)d_in[15];
    const float* rgb_b   = (const float*)d_in[16];
    const float* msr_w   = (const float*)d_in[17];
    const float* msr_b   = (const float*)d_in[18];

    float* out = (float*)d_out;
    float* out_rgb = out;                       // (4,3,64,64)
    float* out_h   = out + 4 * 3 * 64 * 64;     // (4,512,64,64)

    float *px0, *px1, *pd0, *pd1, *ps1;
    cudaGetSymbolAddress((void**)&px0, g_x0);
    cudaGetSymbolAddress((void**)&px1, g_x1);
    cudaGetSymbolAddress((void**)&pd0, g_d0);
    cudaGetSymbolAddress((void**)&pd1, g_d1);
    cudaGetSymbolAddress((void**)&ps1, g_s1);

    styles_kernel<<<768, 256>>>(w, ms0_w, ms0_b, ms1_w, ms1_b, msr_w, msr_b);
    q_kernel<<<(2 * C * C + 255) / 256, 256>>>(conv0_w, conv1_w);
    demod_kernel<<<(2 * BB * C * 32 + 255) / 256, 256>>>();
    upsample_scale_kernel<<<(BB * C * H2 * H2) / 256, 256>>>(maps);

    // layer 0: conv(g_x0) -> d0, bias, noise, lrelu, *s1 -> g_x1
    conv3x3_kernel<<<dim3(8, 16, BB), 256>>>(px0, conv0_w, conv0_b, ns0, noise0,
                                             pd0, ps1, px1, 1);
    // layer 1: conv(g_x1) -> d1, bias, noise, lrelu -> out_h
    conv3x3_kernel<<<dim3(8, 16, BB), 256>>>(px1, conv1_w, conv1_b, ns1, noise1,
                                             pd1, nullptr, out_h, 0);

    rgb_kernel<<<BB * 64, 256>>>(rgb, rgb_w, rgb_b, out_h, out_rgb);
}

// round 8
// speedup vs baseline: 1.6235x; 1.0065x over previous
#include <cuda_runtime.h>
#include <math.h>

#define BB 4
#define C 512
#define HS 32
#define H2 64

// ---------------- scratch (no allocations allowed) ----------------
__device__ float g_s0[BB * C];
__device__ float g_s1[BB * C];
__device__ float g_sr[BB * C];
__device__ float g_d0[BB * C];
__device__ float g_d1[BB * C];
__device__ float g_Q[2 * C * C];
__device__ float g_x0[(size_t)BB * C * H2 * H2];   // s0-scaled upsampled maps
__device__ float g_x1[(size_t)BB * C * H2 * H2];   // s1-scaled lrelu(layer0)

__device__ __forceinline__ float conv_scale() {
    // sqrt(2/1.04) / sqrt(512*9)
    return 1.3867504905630728f / 67.88225099390857f;
}
__device__ __forceinline__ float ms_scale() {
    return 0.04419417382415922f;  // sqrt(2/1024)
}
__device__ __forceinline__ float rgb_scale() {
    return 1.3867504905630728f * 0.06231769651245859f;  // _G * sqrt(2/515)
}

// ---------------- styles: s = w @ (ms_w.T * MS) + ms_b -------------
__global__ void styles_kernel(const float* __restrict__ w,
                              const float* __restrict__ ms0_w, const float* __restrict__ ms0_b,
                              const float* __restrict__ ms1_w, const float* __restrict__ ms1_b,
                              const float* __restrict__ msr_w, const float* __restrict__ msr_b)
{
    int gw = (blockIdx.x * blockDim.x + threadIdx.x) >> 5;
    int lane = threadIdx.x & 31;
    if (gw >= 3 * BB * C) return;
    int which = gw / (BB * C);
    int rem = gw % (BB * C);
    int b = rem / C;
    int i = rem % C;
    const float* msw = which == 0 ? ms0_w : which == 1 ? ms1_w : msr_w;
    const float* msb = which == 0 ? ms0_b : which == 1 ? ms1_b : msr_b;
    const float* wr = w + b * C;
    const float* mr = msw + i * C;
    float acc = 0.f;
    for (int j = lane; j < C; j += 32) acc += wr[j] * mr[j];
#pragma unroll
    for (int o = 16; o; o >>= 1) acc += __shfl_xor_sync(0xffffffffu, acc, o);
    if (lane == 0) {
        float s = acc * ms_scale() + msb[i];
        float* dst = which == 0 ? g_s0 : which == 1 ? g_s1 : g_sr;
        dst[b * C + i] = s;
    }
}

// ---------------- Q[co,ci] = sum_t (W*scale)^2 ---------------------
__global__ void q_kernel(const float* __restrict__ w0, const float* __restrict__ w1)
{
    int idx = blockIdx.x * blockDim.x + threadIdx.x;
    if (idx >= 2 * C * C) return;
    const float* W = idx < C * C ? w0 : w1;
    int e = idx < C * C ? idx : idx - C * C;
    const float* p = W + (size_t)e * 9;
    float s = 0.f;
#pragma unroll
    for (int t = 0; t < 9; t++) s += p[t] * p[t];
    float cs = conv_scale();
    g_Q[idx] = s * cs * cs;
}

// ---------------- d[b,co] = rsqrt(sum_ci Q*s^2 + 1e-8) ------------
__global__ void demod_kernel()
{
    int gw = (blockIdx.x * blockDim.x + threadIdx.x) >> 5;
    int lane = threadIdx.x & 31;
    if (gw >= 2 * BB * C) return;
    int layer = gw / (BB * C);
    int rem = gw % (BB * C);
    int b = rem / C;
    int co = rem % C;
    const float* Q = g_Q + (size_t)layer * C * C + (size_t)co * C;
    const float* s = (layer ? g_s1 : g_s0) + b * C;
    float acc = 0.f;
    for (int ci = lane; ci < C; ci += 32) {
        float sv = s[ci];
        acc += Q[ci] * sv * sv;
    }
#pragma unroll
    for (int o = 16; o; o >>= 1) acc += __shfl_xor_sync(0xffffffffu, acc, o);
    if (lane == 0) (layer ? g_d1 : g_d0)[b * C + co] = rsqrtf(acc + 1e-8f);
}

// ---------------- upsample maps 32->64 bilinear, scale by s0 -------
__global__ void upsample_scale_kernel(const float* __restrict__ maps)
{
    int idx = blockIdx.x * blockDim.x + threadIdx.x;
    if (idx >= BB * C * H2 * H2) return;
    int x = idx & 63;
    int y = (idx >> 6) & 63;
    int c = (idx >> 12) & (C - 1);
    int b = idx >> 21;
    float sy = 0.5f * y - 0.25f;
    float sx = 0.5f * x - 0.25f;
    int yi = (int)floorf(sy);
    int xi = (int)floorf(sx);
    float wy = sy - yi;
    float wx = sx - xi;
    int ya = yi < 0 ? 0 : yi;
    int yb = yi + 1 > HS - 1 ? HS - 1 : yi + 1;
    int xa = xi < 0 ? 0 : xi;
    int xb = xi + 1 > HS - 1 ? HS - 1 : xi + 1;
    const float* m = maps + ((size_t)b * C + c) * HS * HS;
    float v = (1.f - wy) * ((1.f - wx) * m[ya * HS + xa] + wx * m[ya * HS + xb]) +
              wy * ((1.f - wx) * m[yb * HS + xa] + wx * m[yb * HS + xb]);
    g_x0[idx] = v * g_s0[b * C + c];
}

// ---------------- 3x3 conv, d-scale + bias + noise + lrelu (+s1) ---
// Block: 64 out-channels x (4 rows x 64 cols). Thread: 8 co x 8 px (px stride 8).
__global__ __launch_bounds__(256)
void conv3x3_kernel(const float* __restrict__ xin, const float* __restrict__ Wg,
                    const float* __restrict__ bias, const float* __restrict__ ns,
                    const float* __restrict__ noise, const float* __restrict__ dmod,
                    const float* __restrict__ snext, float* __restrict__ out,
                    int scale_out)
{
    __shared__ float sX[4 * 6 * 72];   // [ci=4][row=6 (y0-1..y0+4)][col=66 pad 72]
    __shared__ float sW[4 * 9 * 64];   // [ci][tap][co]

    const int tid = threadIdx.x;
    const int cog = tid >> 5;          // 0..7, co sub-block
    const int lane = tid & 31;
    const int tx = lane & 7;           // pixel base within row (stride-8 ownership)
    const int ty = lane >> 3;          // row 0..3
    const int co0 = blockIdx.x * 64;
    const int y0 = blockIdx.y * 4;
    const int b = blockIdx.z;
    const float cs = conv_scale();

    float acc[8][8];
#pragma unroll
    for (int k = 0; k < 8; k++)
#pragma unroll
        for (int j = 0; j < 8; j++) acc[k][j] = 0.f;

    const float* xb = xin + (size_t)b * C * H2 * H2;

#pragma unroll 1
    for (int ci0 = 0; ci0 < C; ci0 += 4) {
        __syncthreads();
        // input tile: 4 ci x 6 rows x 66 cols (zero-padded borders)
        for (int idx = tid; idx < 4 * 6 * 66; idx += 256) {
            int c = idx / 396;
            int rem = idx - c * 396;
            int r = rem / 66;
            int col = rem - r * 66;
            int y = y0 - 1 + r;
            int x = col - 1;
            float v = 0.f;
            if ((unsigned)y < 64u && (unsigned)x < 64u)
                v = xb[(((size_t)(ci0 + c)) * 64 + y) * 64 + x];
            sX[(c * 6 + r) * 72 + col] = v;
        }
        // weights: [ci][tap][co]
        for (int idx = tid; idx < 2304; idx += 256) {
            int co = idx & 63;
            int t = (idx >> 6) % 9;
            int c = idx / 576;
            sW[(c * 9 + t) * 64 + co] =
                Wg[(((size_t)(co0 + co)) * C + (ci0 + c)) * 9 + t] * cs;
        }
        __syncthreads();

#pragma unroll 1
        for (int c = 0; c < 4; c++) {
#pragma unroll
            for (int dy = 0; dy < 3; dy++) {
                const float* xr = &sX[(c * 6 + ty + dy) * 72];
#pragma unroll
                for (int dx = 0; dx < 3; dx++) {
                    const float* wp = &sW[(c * 9 + dy * 3 + dx) * 64 + cog * 8];
                    float wv[8];
#pragma unroll
                    for (int k = 0; k < 8; k++) wv[k] = wp[k];
#pragma unroll
                    for (int j = 0; j < 8; j++) {
                        float xv = xr[tx + 8 * j + dx];
#pragma unroll
                        for (int k = 0; k < 8; k++)
                            acc[k][j] = fmaf(wv[k], xv, acc[k][j]);
                    }
                }
            }
        }
    }

    // epilogue
    const int y = y0 + ty;
    const float* np = noise + ((size_t)b * 64 + y) * 64;
#pragma unroll
    for (int k = 0; k < 8; k++) {
        const int co = co0 + cog * 8 + k;
        const float dv = dmod[b * C + co];
        const float bv = bias[co];
        const float nv = ns[co];
        const float sv = scale_out ? snext[b * C + co] : 1.f;
        float* op = out + (((size_t)b * C + co) * 64 + y) * 64;
#pragma unroll
        for (int j = 0; j < 8; j++) {
            const int x = tx + 8 * j;
            float v = acc[k][j] * dv + bv + nv * np[x];
            v = v >= 0.f ? v : 0.2f * v;
            op[x] = v * sv;
        }
    }
}

// ---------------- to_rgb: rgb_up + 1x1 modulated conv --------------
__global__ void rgb_kernel(const float* __restrict__ rgb_in, const float* __restrict__ rgb_w,
                           const float* __restrict__ rgb_b, const float* __restrict__ h,
                           float* __restrict__ out)
{
    __shared__ float coef[3 * C];
    __shared__ float part[4][3][64];
    int b = blockIdx.x >> 6;
    int y = blockIdx.x & 63;
    int tid = threadIdx.x;
    const float rs = rgb_scale();
    for (int i = tid; i < 3 * C; i += 256) {
        int c2 = i >> 9;
        int co = i & (C - 1);
        coef[i] = rgb_w[c2 * C + co] * rs * g_sr[b * C + co];
    }
    __syncthreads();
    int px = tid & 63;
    int cg = tid >> 6;
    float a0 = 0.f, a1 = 0.f, a2 = 0.f;
    const float* hp = h + (((size_t)b * C + cg * 128) * 64 + y) * 64 + px;
    const float* c0 = coef + cg * 128;
    for (int co = 0; co < 128; co++) {
        float hv = hp[(size_t)co * 4096];
        a0 += c0[co] * hv;
        a1 += c0[C + co] * hv;
        a2 += c0[2 * C + co] * hv;
    }
    part[cg][0][px] = a0;
    part[cg][1][px] = a1;
    part[cg][2][px] = a2;
    __syncthreads();
    if (tid < 192) {
        int c2 = tid / 64;
        int x = tid % 64;
        float s = part[0][c2][x] + part[1][c2][x] + part[2][c2][x] + part[3][c2][x];
        float sy = 0.5f * y - 0.25f;
        float sx = 0.5f * x - 0.25f;
        int yi = (int)floorf(sy);
        int xi = (int)floorf(sx);
        float wy = sy - yi;
        float wx = sx - xi;
        int ya = yi < 0 ? 0 : yi;
        int yb = yi + 1 > HS - 1 ? HS - 1 : yi + 1;
        int xa = xi < 0 ? 0 : xi;
        int xb2 = xi + 1 > HS - 1 ? HS - 1 : xi + 1;
        const float* rp = rgb_in + ((size_t)b * 3 + c2) * HS * HS;
        float up = (1.f - wy) * ((1.f - wx) * rp[ya * HS + xa] + wx * rp[ya * HS + xb2]) +
                   wy * ((1.f - wx) * rp[yb * HS + xa] + wx * rp[yb * HS + xb2]);
        out[(((size_t)b * 3 + c2) * 64 + y) * 64 + x] = up + rgb_b[c2] + s;
    }
}

// ---------------- launch ------------------------------------------
extern "C" void kernel_launch(void* const* d_in, const int* in_sizes, int n_in,
                              void* d_out, int out_size)
{
    const float* maps    = (const float*)d_in[0];
    const float* w       = (const float*)d_in[1];
    const float* rgb     = (const float*)d_in[2];
    const float* noise0  = (const float*)d_in[3];
    const float* noise1  = (const float*)d_in[4];
    const float* conv0_w = (const float*)d_in[5];
    const float* conv0_b = (const float*)d_in[6];
    const float* ms0_w   = (const float*)d_in[7];
    const float* ms0_b   = (const float*)d_in[8];
    const float* ns0     = (const float*)d_in[9];
    const float* conv1_w = (const float*)d_in[10];
    const float* conv1_b = (const float*)d_in[11];
    const float* ms1_w   = (const float*)d_in[12];
    const float* ms1_b   = (const float*)d_in[13];
    const float* ns1     = (const float*)d_in[14];
    const float* rgb_w   = (const float*)d_in[15];
    const float* rgb_b   = (const float*)d_in[16];
    const float* msr_w   = (const float*)d_in[17];
    const float* msr_b   = (const float*)d_in[18];

    float* out = (float*)d_out;
    float* out_rgb = out;                       // (4,3,64,64)
    float* out_h   = out + 4 * 3 * 64 * 64;     // (4,512,64,64)

    float *px0, *px1, *pd0, *pd1, *ps1;
    cudaGetSymbolAddress((void**)&px0, g_x0);
    cudaGetSymbolAddress((void**)&px1, g_x1);
    cudaGetSymbolAddress((void**)&pd0, g_d0);
    cudaGetSymbolAddress((void**)&pd1, g_d1);
    cudaGetSymbolAddress((void**)&ps1, g_s1);

    styles_kernel<<<768, 256>>>(w, ms0_w, ms0_b, ms1_w, ms1_b, msr_w, msr_b);
    q_kernel<<<(2 * C * C + 255) / 256, 256>>>(conv0_w, conv1_w);
    demod_kernel<<<(2 * BB * C * 32 + 255) / 256, 256>>>();
    upsample_scale_kernel<<<(BB * C * H2 * H2) / 256, 256>>>(maps);

    // layer 0: conv(g_x0) -> d0, bias, noise, lrelu, *s1 -> g_x1
    conv3x3_kernel<<<dim3(8, 16, BB), 256>>>(px0, conv0_w, conv0_b, ns0, noise0,
                                             pd0, ps1, px1, 1);
    // layer 1: conv(g_x1) -> d1, bias, noise, lrelu -> out_h
    conv3x3_kernel<<<dim3(8, 16, BB), 256>>>(px1, conv1_w, conv1_b, ns1, noise1,
                                             pd1, nullptr, out_h, 0);

    rgb_kernel<<<BB * 64, 256>>>(rgb, rgb_w, rgb_b, out_h, out_rgb);
}

// round 12
// speedup vs baseline: 5.3121x; 3.2720x over previous
#include <cuda_runtime.h>
#include <cuda_bf16.h>
#include <math.h>
#include <stdint.h>

#define BB 4
#define C 512
#define HS 32
#define H2 64
#define KT 24
#define AROWS 4224
#define NCHUNK 216
#define NST 3
#define STAGE_B 32768
#define SM_GEMM (NST * STAGE_B)   /* 98304 */

// ---------------- scratch ----------------
__device__ float g_s0[BB * C];
__device__ float g_s1[BB * C];
__device__ float g_sr[BB * C];
__device__ float g_d0[BB * C];
__device__ float g_d1[BB * C];
__device__ float g_Q[2 * C * C];
__device__ float g_x0[(size_t)BB * C * H2 * H2];
__device__ float g_x1[(size_t)BB * C * H2 * H2];
__device__ __align__(1024) unsigned char g_Ah[(size_t)BB * KT * AROWS * 128];
__device__ __align__(1024) unsigned char g_Al[(size_t)BB * KT * AROWS * 128];
__device__ __align__(1024) unsigned char g_Bh[(size_t)2 * 3 * KT * 512 * 128];
__device__ __align__(1024) unsigned char g_Bl[(size_t)2 * 3 * KT * 512 * 128];

__device__ __forceinline__ float conv_scale() {
    return 1.3867504905630728f / 67.88225099390857f;
}
__device__ __forceinline__ float ms_scale() { return 0.04419417382415922f; }
__device__ __forceinline__ float rgb_scale() {
    return 1.3867504905630728f * 0.06231769651245859f;
}

// ---------------- PTX helpers (baseline ISA only: sm_80-class) -----
__device__ __forceinline__ uint32_t smem_u32(const void* p) {
    uint32_t a;
    asm("{ .reg .u64 t; cvta.to.shared.u64 t, %1; cvt.u32.u64 %0, t; }" : "=r"(a) : "l"(p));
    return a;
}
#define CP_ASYNC16(dst, src) \
    asm volatile("cp.async.cg.shared.global [%0], [%1], 16;" :: "r"(dst), "l"(src))
#define CP_COMMIT() asm volatile("cp.async.commit_group;" ::: "memory")
#define CP_WAIT2() asm volatile("cp.async.wait_group 2;" ::: "memory")
#define CP_WAIT0() asm volatile("cp.async.wait_group 0;" ::: "memory")

__device__ __forceinline__ void ldsm4(uint32_t* r, uint32_t addr) {
    asm volatile("ldmatrix.sync.aligned.m8n8.x4.shared.b16 {%0,%1,%2,%3}, [%4];"
        : "=r"(r[0]), "=r"(r[1]), "=r"(r[2]), "=r"(r[3]) : "r"(addr));
}
__device__ __forceinline__ void mma_bf16(float* c, const uint32_t* a,
                                         uint32_t b0, uint32_t b1) {
    asm volatile("mma.sync.aligned.m16n8k16.row.col.f32.bf16.bf16.f32 "
        "{%0,%1,%2,%3}, {%4,%5,%6,%7}, {%8,%9}, {%0,%1,%2,%3};"
        : "+f"(c[0]), "+f"(c[1]), "+f"(c[2]), "+f"(c[3])
        : "r"(a[0]), "r"(a[1]), "r"(a[2]), "r"(a[3]), "r"(b0), "r"(b1));
}

// ---------------- styles ----------------
__global__ void styles_kernel(const float* __restrict__ w,
                              const float* __restrict__ ms0_w, const float* __restrict__ ms0_b,
                              const float* __restrict__ ms1_w, const float* __restrict__ ms1_b,
                              const float* __restrict__ msr_w, const float* __restrict__ msr_b)
{
    int gw = (blockIdx.x * blockDim.x + threadIdx.x) >> 5;
    int lane = threadIdx.x & 31;
    if (gw >= 3 * BB * C) return;
    int which = gw / (BB * C);
    int rem = gw % (BB * C);
    int b = rem / C;
    int i = rem % C;
    const float* msw = which == 0 ? ms0_w : which == 1 ? ms1_w : msr_w;
    const float* msb = which == 0 ? ms0_b : which == 1 ? ms1_b : msr_b;
    const float* wr = w + b * C;
    const float* mr = msw + i * C;
    float acc = 0.f;
    for (int j = lane; j < C; j += 32) acc += wr[j] * mr[j];
#pragma unroll
    for (int o = 16; o; o >>= 1) acc += __shfl_xor_sync(0xffffffffu, acc, o);
    if (lane == 0) {
        float s = acc * ms_scale() + msb[i];
        (which == 0 ? g_s0 : which == 1 ? g_s1 : g_sr)[b * C + i] = s;
    }
}

__global__ void q_kernel(const float* __restrict__ w0, const float* __restrict__ w1)
{
    int idx = blockIdx.x * blockDim.x + threadIdx.x;
    if (idx >= 2 * C * C) return;
    const float* W = idx < C * C ? w0 : w1;
    int e = idx < C * C ? idx : idx - C * C;
    const float* p = W + (size_t)e * 9;
    float s = 0.f;
#pragma unroll
    for (int t = 0; t < 9; t++) s += p[t] * p[t];
    float cs = conv_scale();
    g_Q[idx] = s * cs * cs;
}

__global__ void demod_kernel()
{
    int gw = (blockIdx.x * blockDim.x + threadIdx.x) >> 5;
    int lane = threadIdx.x & 31;
    if (gw >= 2 * BB * C) return;
    int layer = gw / (BB * C);
    int rem = gw % (BB * C);
    int b = rem / C;
    int co = rem % C;
    const float* Q = g_Q + (size_t)layer * C * C + (size_t)co * C;
    const float* s = (layer ? g_s1 : g_s0) + b * C;
    float acc = 0.f;
    for (int ci = lane; ci < C; ci += 32) { float sv = s[ci]; acc += Q[ci] * sv * sv; }
#pragma unroll
    for (int o = 16; o; o >>= 1) acc += __shfl_xor_sync(0xffffffffu, acc, o);
    if (lane == 0) (layer ? g_d1 : g_d0)[b * C + co] = rsqrtf(acc + 1e-8f);
}

__global__ void upsample_scale_kernel(const float* __restrict__ maps)
{
    int idx = blockIdx.x * blockDim.x + threadIdx.x;
    if (idx >= BB * C * H2 * H2) return;
    int x = idx & 63;
    int y = (idx >> 6) & 63;
    int c = (idx >> 12) & (C - 1);
    int b = idx >> 21;
    float sy = 0.5f * y - 0.25f;
    float sx = 0.5f * x - 0.25f;
    int yi = (int)floorf(sy);
    int xi = (int)floorf(sx);
    float wy = sy - yi;
    float wx = sx - xi;
    int ya = yi < 0 ? 0 : yi;
    int yb = yi + 1 > HS - 1 ? HS - 1 : yi + 1;
    int xa = xi < 0 ? 0 : xi;
    int xb = xi + 1 > HS - 1 ? HS - 1 : xi + 1;
    const float* m = maps + ((size_t)b * C + c) * HS * HS;
    float v = (1.f - wy) * ((1.f - wx) * m[ya * HS + xa] + wx * m[ya * HS + xb]) +
              wy * ((1.f - wx) * m[yb * HS + xa] + wx * m[yb * HS + xb]);
    g_x0[idx] = v * g_s0[b * C + c];
}

// ---------------- prep A: x -> bf16 hi/lo slabs (plain row-major) --
// slab[b][kt=dx*8+cig][row=pr*64+xm][cc 0..63]; value = X(ci, pr-1, xm+dx-1)
__global__ __launch_bounds__(256)
void prep_A_kernel(const float* __restrict__ x)
{
    __shared__ float tile[64][65];
    const int prg = blockIdx.x;   // 0..65
    const int cig = blockIdx.y;   // 0..7
    const int b = blockIdx.z;
    const int tid = threadIdx.x;
    const int y = prg - 1;
    if ((unsigned)y < 64u) {
        const float* xp = x + (size_t)(b * C + cig * 64) * 4096 + y * 64;
        for (int i = tid; i < 4096; i += 256)
            tile[i >> 6][i & 63] = xp[(size_t)(i >> 6) * 4096 + (i & 63)];
    } else {
        for (int i = tid; i < 4096; i += 256) tile[i >> 6][i & 63] = 0.f;
    }
    __syncthreads();
#pragma unroll
    for (int dx = 0; dx < 3; dx++) {
        const int kt = dx * 8 + cig;
        const size_t slab = ((size_t)(b * KT + kt) * AROWS + (size_t)prg * 64) * 128;
        unsigned char* hs = g_Ah + slab;
        unsigned char* ls = g_Al + slab;
        for (int i = tid; i < 4096; i += 256) {
            int xm = i >> 6;
            int cc = i & 63;
            int xv = xm + dx - 1;
            float v = ((unsigned)xv < 64u) ? tile[cc][xv] : 0.f;
            __nv_bfloat16 h = __float2bfloat16(v);
            __nv_bfloat16 l = __float2bfloat16(v - __bfloat162float(h));
            uint32_t off = (uint32_t)xm * 128 + cc * 2;
            *(__nv_bfloat16*)(hs + off) = h;
            *(__nv_bfloat16*)(ls + off) = l;
        }
    }
}

// ---------------- prep B: weights -> bf16 hi/lo [layer][dy][kt][co][cc]
__global__ void prep_B_kernel(const float* __restrict__ w0, const float* __restrict__ w1)
{
    int idx = blockIdx.x * blockDim.x + threadIdx.x;
    if (idx >= 2 * 3 * KT * 512 * 64) return;
    int cc = idx & 63;
    int t = idx >> 6;
    int co = t & 511; t >>= 9;
    int kt = t % KT; t /= KT;
    int dy = t % 3;
    int layer = t / 3;
    int ci = (kt & 7) * 64 + cc;
    int dx = kt >> 3;
    const float* W = layer ? w1 : w0;
    float v = W[(((size_t)co * C + ci) * 3 + dy) * 3 + dx] * conv_scale();
    __nv_bfloat16 h = __float2bfloat16(v);
    __nv_bfloat16 l = __float2bfloat16(v - __bfloat162float(h));
    uint32_t off = (uint32_t)co * 128 + cc * 2;
    size_t slab = (size_t)((layer * 3 + dy) * KT + kt) * 65536;
    *(__nv_bfloat16*)(g_Bh + slab + off) = h;
    *(__nv_bfloat16*)(g_Bl + slab + off) = l;
}

// ---------------- HMMA conv GEMM ----------------------------------
// CTA: 128 px (2 output rows) x 128 co. 8 warps (2x4), warp 64x32.
// 216 K-chunks of 64 = 3 splits x 3 dy x 24 kt. cp.async 3-stage pipe.
__global__ __launch_bounds__(256, 2)
void hgemm_conv_kernel(const unsigned char* __restrict__ Ah, const unsigned char* __restrict__ Al,
                       const unsigned char* __restrict__ Bh, const unsigned char* __restrict__ Bl,
                       const float* __restrict__ dmod, const float* __restrict__ bias,
                       const float* __restrict__ ns, const float* __restrict__ noise,
                       const float* __restrict__ snext, float* __restrict__ out)
{
    extern __shared__ unsigned char sm[];
    const uint32_t sb = smem_u32(sm);
    const int tid = threadIdx.x;
    const int wid = tid >> 5;
    const int lane = tid & 31;
    const int tm = blockIdx.x;
    const int nb = blockIdx.y;
    const int b = blockIdx.z;
    const int warp_m = wid >> 2;
    const int warp_n = wid & 3;

    auto load_stage = [&](int s) {
        int pass = s / 72, r = s % 72, dy = r / 24, kt = r % 24;
        const unsigned char* ga = (pass == 1 ? Al : Ah) +
            (((size_t)(b * KT + kt) * AROWS + (size_t)(2 * tm + dy) * 64) << 7);
        const unsigned char* gb = (pass == 2 ? Bl : Bh) +
            ((size_t)((dy * KT + kt) * 512 + nb * 128) << 7);
        uint32_t buf = sb + (uint32_t)(s % NST) * STAGE_B;
#pragma unroll
        for (int i = 0; i < 4; i++) {
            int id = tid + i * 256;
            int row = id >> 3, c = id & 7;
            uint32_t sw = (uint32_t)(c ^ (row & 7)) << 4;
            CP_ASYNC16(buf + (row << 7) + sw, ga + ((size_t)id << 4));
            CP_ASYNC16(buf + 16384u + (row << 7) + sw, gb + ((size_t)id << 4));
        }
    };

    float acc[4][4][4];
#pragma unroll
    for (int mi = 0; mi < 4; mi++)
#pragma unroll
        for (int nj = 0; nj < 4; nj++)
#pragma unroll
            for (int q = 0; q < 4; q++) acc[mi][nj][q] = 0.f;

    load_stage(0); CP_COMMIT();
    load_stage(1); CP_COMMIT();
    load_stage(2); CP_COMMIT();

#pragma unroll 1
    for (int s = 0; s < NCHUNK; s++) {
        CP_WAIT2();
        __syncthreads();
        uint32_t sA = sb + (uint32_t)(s % NST) * STAGE_B;
        uint32_t sB = sA + 16384u;
#pragma unroll
        for (int ks = 0; ks < 4; ks++) {
            uint32_t afr[4][4];
            uint32_t bfr[2][4];
            const int c = ks * 2 + (lane >> 4);
#pragma unroll
            for (int mi = 0; mi < 4; mi++) {
                int m = warp_m * 64 + mi * 16 + (lane & 15);
                ldsm4(afr[mi], sA + ((uint32_t)m << 7) + ((uint32_t)(c ^ (m & 7)) << 4));
            }
#pragma unroll
            for (int bj = 0; bj < 2; bj++) {
                int n = warp_n * 32 + bj * 16 + (lane & 15);
                ldsm4(bfr[bj], sB + ((uint32_t)n << 7) + ((uint32_t)(c ^ (n & 7)) << 4));
            }
#pragma unroll
            for (int mi = 0; mi < 4; mi++)
#pragma unroll
                for (int nj = 0; nj < 4; nj++)
                    mma_bf16(acc[mi][nj], afr[mi],
                             bfr[nj >> 1][nj & 1], bfr[nj >> 1][(nj & 1) + 2]);
        }
        __syncthreads();
        if (s + NST < NCHUNK) load_stage(s + NST);
        CP_COMMIT();
    }
    CP_WAIT0();
    __syncthreads();

    // transpose through smem -> coalesced stores, fused epilogue
    float* T = (float*)sm;   // [128 co][132]
#pragma unroll
    for (int mi = 0; mi < 4; mi++)
#pragma unroll
        for (int nj = 0; nj < 4; nj++) {
            int p0 = warp_m * 64 + mi * 16 + (lane >> 2);
            int n0 = warp_n * 32 + nj * 8 + (lane & 3) * 2;
            T[(n0    ) * 132 + p0    ] = acc[mi][nj][0];
            T[(n0 + 1) * 132 + p0    ] = acc[mi][nj][1];
            T[(n0    ) * 132 + p0 + 8] = acc[mi][nj][2];
            T[(n0 + 1) * 132 + p0 + 8] = acc[mi][nj][3];
        }
    __syncthreads();
    {
        const int co = tid >> 1;
        const int half = tid & 1;
        const int cog = nb * 128 + co;
        const float dv = dmod[b * C + cog];
        const float bv = bias[cog];
        const float nv = ns[cog];
        const float sv = snext ? snext[b * C + cog] : 1.f;
        const int y = 2 * tm + half;
        const float* np = noise + ((size_t)b * 64 + y) * 64;
        float* op = out + ((size_t)(b * C + cog) * 64 + y) * 64;
        const float* tr = T + co * 132 + half * 64;
#pragma unroll
        for (int x4 = 0; x4 < 16; x4++) {
            float4 t = *(const float4*)(tr + x4 * 4);
            float4 n4 = *(const float4*)(np + x4 * 4);
            float4 o;
            float v;
            v = t.x * dv + bv + nv * n4.x; v = v >= 0.f ? v : 0.2f * v; o.x = v * sv;
            v = t.y * dv + bv + nv * n4.y; v = v >= 0.f ? v : 0.2f * v; o.y = v * sv;
            v = t.z * dv + bv + nv * n4.z; v = v >= 0.f ? v : 0.2f * v; o.z = v * sv;
            v = t.w * dv + bv + nv * n4.w; v = v >= 0.f ? v : 0.2f * v; o.w = v * sv;
            *(float4*)(op + x4 * 4) = o;
        }
    }
}

// ---------------- to_rgb ------------------------------------------
__global__ void rgb_kernel(const float* __restrict__ rgb_in, const float* __restrict__ rgb_w,
                           const float* __restrict__ rgb_b, const float* __restrict__ h,
                           float* __restrict__ out)
{
    __shared__ float coef[3 * C];
    __shared__ float part[4][3][64];
    int b = blockIdx.x >> 6;
    int y = blockIdx.x & 63;
    int tid = threadIdx.x;
    const float rs = rgb_scale();
    for (int i = tid; i < 3 * C; i += 256) {
        int c2 = i >> 9;
        int co = i & (C - 1);
        coef[i] = rgb_w[c2 * C + co] * rs * g_sr[b * C + co];
    }
    __syncthreads();
    int px = tid & 63;
    int cg = tid >> 6;
    float a0 = 0.f, a1 = 0.f, a2 = 0.f;
    const float* hp = h + (((size_t)b * C + cg * 128) * 64 + y) * 64 + px;
    const float* c0 = coef + cg * 128;
    for (int co = 0; co < 128; co++) {
        float hv = hp[(size_t)co * 4096];
        a0 += c0[co] * hv;
        a1 += c0[C + co] * hv;
        a2 += c0[2 * C + co] * hv;
    }
    part[cg][0][px] = a0;
    part[cg][1][px] = a1;
    part[cg][2][px] = a2;
    __syncthreads();
    if (tid < 192) {
        int c2 = tid / 64;
        int x = tid % 64;
        float s = part[0][c2][x] + part[1][c2][x] + part[2][c2][x] + part[3][c2][x];
        float sy = 0.5f * y - 0.25f;
        float sx = 0.5f * x - 0.25f;
        int yi = (int)floorf(sy);
        int xi = (int)floorf(sx);
        float wy = sy - yi;
        float wx = sx - xi;
        int ya = yi < 0 ? 0 : yi;
        int yb = yi + 1 > HS - 1 ? HS - 1 : yi + 1;
        int xa = xi < 0 ? 0 : xi;
        int xb2 = xi + 1 > HS - 1 ? HS - 1 : xi + 1;
        const float* rp = rgb_in + ((size_t)b * 3 + c2) * HS * HS;
        float up = (1.f - wy) * ((1.f - wx) * rp[ya * HS + xa] + wx * rp[ya * HS + xb2]) +
                   wy * ((1.f - wx) * rp[yb * HS + xa] + wx * rp[yb * HS + xb2]);
        out[(((size_t)b * 3 + c2) * 64 + y) * 64 + x] = up + rgb_b[c2] + s;
    }
}

// ---------------- launch ------------------------------------------
extern "C" void kernel_launch(void* const* d_in, const int* in_sizes, int n_in,
                              void* d_out, int out_size)
{
    const float* maps    = (const float*)d_in[0];
    const float* w       = (const float*)d_in[1];
    const float* rgb     = (const float*)d_in[2];
    const float* noise0  = (const float*)d_in[3];
    const float* noise1  = (const float*)d_in[4];
    const float* conv0_w = (const float*)d_in[5];
    const float* conv0_b = (const float*)d_in[6];
    const float* ms0_w   = (const float*)d_in[7];
    const float* ms0_b   = (const float*)d_in[8];
    const float* ns0     = (const float*)d_in[9];
    const float* conv1_w = (const float*)d_in[10];
    const float* conv1_b = (const float*)d_in[11];
    const float* ms1_w   = (const float*)d_in[12];
    const float* ms1_b   = (const float*)d_in[13];
    const float* ns1     = (const float*)d_in[14];
    const float* rgb_w   = (const float*)d_in[15];
    const float* rgb_b   = (const float*)d_in[16];
    const float* msr_w   = (const float*)d_in[17];
    const float* msr_b   = (const float*)d_in[18];

    float* out = (float*)d_out;
    float* out_rgb = out;
    float* out_h   = out + 4 * 3 * 64 * 64;

    float *px0, *px1, *pd0, *pd1, *ps1;
    unsigned char *pAh, *pAl, *pBh, *pBl;
    cudaGetSymbolAddress((void**)&px0, g_x0);
    cudaGetSymbolAddress((void**)&px1, g_x1);
    cudaGetSymbolAddress((void**)&pd0, g_d0);
    cudaGetSymbolAddress((void**)&pd1, g_d1);
    cudaGetSymbolAddress((void**)&ps1, g_s1);
    cudaGetSymbolAddress((void**)&pAh, g_Ah);
    cudaGetSymbolAddress((void**)&pAl, g_Al);
    cudaGetSymbolAddress((void**)&pBh, g_Bh);
    cudaGetSymbolAddress((void**)&pBl, g_Bl);

    cudaFuncSetAttribute(hgemm_conv_kernel,
                         cudaFuncAttributeMaxDynamicSharedMemorySize, SM_GEMM);

    styles_kernel<<<768, 256>>>(w, ms0_w, ms0_b, ms1_w, ms1_b, msr_w, msr_b);
    q_kernel<<<(2 * C * C + 255) / 256, 256>>>(conv0_w, conv1_w);
    demod_kernel<<<(2 * BB * C * 32 + 255) / 256, 256>>>();
    upsample_scale_kernel<<<(BB * C * H2 * H2) / 256, 256>>>(maps);
    prep_B_kernel<<<(2 * 3 * KT * 512 * 64 + 255) / 256, 256>>>(conv0_w, conv1_w);

    const size_t bl_off = (size_t)3 * KT * 65536;

    prep_A_kernel<<<dim3(66, 8, BB), 256>>>(px0);
    hgemm_conv_kernel<<<dim3(32, 4, BB), 256, SM_GEMM>>>(
        pAh, pAl, pBh, pBl, pd0, conv0_b, ns0, noise0, ps1, px1);

    prep_A_kernel<<<dim3(66, 8, BB), 256>>>(px1);
    hgemm_conv_kernel<<<dim3(32, 4, BB), 256, SM_GEMM>>>(
        pAh, pAl, pBh + bl_off, pBl + bl_off, pd1, conv1_b, ns1, noise1, nullptr, out_h);

    rgb_kernel<<<BB * 64, 256>>>(rgb, rgb_w, rgb_b, out_h, out_rgb);
}

// round 14
// speedup vs baseline: 5.8408x; 1.0995x over previous
#include <cuda_runtime.h>
#include <cuda_bf16.h>
#include <math.h>
#include <stdint.h>

#define BB 4
#define C 512
#define HS 32
#define H2 64
#define SLAB_ROWS 4356           /* 66x66 padded pixel grid */
#define NSTAGES 72               /* 3 dy x 3 dx x 8 cig */
#define STAGE_B 98304            /* Ah16K + Al16K + Bh32K + Bl32K */
#define SM_GEMM (2 * STAGE_B)    /* 196608 */
#define B_LAYER_OFF ((size_t)72 * 512 * 128)

// ---------------- scratch ----------------
__device__ float g_s0[BB * C];
__device__ float g_s1[BB * C];
__device__ float g_sr[BB * C];
__device__ float g_d0[BB * C];
__device__ float g_d1[BB * C];
__device__ float g_Q[2 * C * C];
__device__ float g_x0[(size_t)BB * C * H2 * H2];
__device__ float g_x1[(size_t)BB * C * H2 * H2];
__device__ __align__(1024) unsigned char g_Ah[(size_t)BB * 8 * SLAB_ROWS * 128];
__device__ __align__(1024) unsigned char g_Al[(size_t)BB * 8 * SLAB_ROWS * 128];
__device__ __align__(1024) unsigned char g_Bh[(size_t)2 * 72 * 512 * 128];
__device__ __align__(1024) unsigned char g_Bl[(size_t)2 * 72 * 512 * 128];

__device__ __forceinline__ float conv_scale() {
    return 1.3867504905630728f / 67.88225099390857f;
}
__device__ __forceinline__ float ms_scale() { return 0.04419417382415922f; }
__device__ __forceinline__ float rgb_scale() {
    return 1.3867504905630728f * 0.06231769651245859f;
}

// ---------------- PTX helpers (baseline ISA) ----------------
__device__ __forceinline__ uint32_t smem_u32(const void* p) {
    uint32_t a;
    asm("{ .reg .u64 t; cvta.to.shared.u64 t, %1; cvt.u32.u64 %0, t; }" : "=r"(a) : "l"(p));
    return a;
}
#define CP_ASYNC16(dst, src) \
    asm volatile("cp.async.cg.shared.global [%0], [%1], 16;" :: "r"(dst), "l"(src))
#define CP_COMMIT() asm volatile("cp.async.commit_group;" ::: "memory")
#define CP_WAIT1() asm volatile("cp.async.wait_group 1;" ::: "memory")
#define CP_WAIT0() asm volatile("cp.async.wait_group 0;" ::: "memory")

__device__ __forceinline__ void ldsm4(uint32_t* r, uint32_t addr) {
    asm volatile("ldmatrix.sync.aligned.m8n8.x4.shared.b16 {%0,%1,%2,%3}, [%4];"
        : "=r"(r[0]), "=r"(r[1]), "=r"(r[2]), "=r"(r[3]) : "r"(addr));
}
__device__ __forceinline__ void mma_bf16(float* c, const uint32_t* a,
                                         uint32_t b0, uint32_t b1) {
    asm volatile("mma.sync.aligned.m16n8k16.row.col.f32.bf16.bf16.f32 "
        "{%0,%1,%2,%3}, {%4,%5,%6,%7}, {%8,%9}, {%0,%1,%2,%3};"
        : "+f"(c[0]), "+f"(c[1]), "+f"(c[2]), "+f"(c[3])
        : "r"(a[0]), "r"(a[1]), "r"(a[2]), "r"(a[3]), "r"(b0), "r"(b1));
}
__device__ __forceinline__ uint32_t pack_bf16(float v0, float v1) {
    __nv_bfloat16 h0 = __float2bfloat16(v0);
    __nv_bfloat16 h1 = __float2bfloat16(v1);
    return (uint32_t)*(unsigned short*)&h0 | ((uint32_t)*(unsigned short*)&h1 << 16);
}
__device__ __forceinline__ float bf16_lo_res(float v) {
    __nv_bfloat16 h = __float2bfloat16(v);
    return v - __bfloat162float(h);
}

// ---------------- styles ----------------
__global__ void styles_kernel(const float* __restrict__ w,
                              const float* __restrict__ ms0_w, const float* __restrict__ ms0_b,
                              const float* __restrict__ ms1_w, const float* __restrict__ ms1_b,
                              const float* __restrict__ msr_w, const float* __restrict__ msr_b)
{
    int gw = (blockIdx.x * blockDim.x + threadIdx.x) >> 5;
    int lane = threadIdx.x & 31;
    if (gw >= 3 * BB * C) return;
    int which = gw / (BB * C);
    int rem = gw % (BB * C);
    int b = rem / C;
    int i = rem % C;
    const float* msw = which == 0 ? ms0_w : which == 1 ? ms1_w : msr_w;
    const float* msb = which == 0 ? ms0_b : which == 1 ? ms1_b : msr_b;
    const float* wr = w + b * C;
    const float* mr = msw + i * C;
    float acc = 0.f;
    for (int j = lane; j < C; j += 32) acc += wr[j] * mr[j];
#pragma unroll
    for (int o = 16; o; o >>= 1) acc += __shfl_xor_sync(0xffffffffu, acc, o);
    if (lane == 0) {
        float s = acc * ms_scale() + msb[i];
        (which == 0 ? g_s0 : which == 1 ? g_s1 : g_sr)[b * C + i] = s;
    }
}

__global__ void q_kernel(const float* __restrict__ w0, const float* __restrict__ w1)
{
    int idx = blockIdx.x * blockDim.x + threadIdx.x;
    if (idx >= 2 * C * C) return;
    const float* W = idx < C * C ? w0 : w1;
    int e = idx < C * C ? idx : idx - C * C;
    const float* p = W + (size_t)e * 9;
    float s = 0.f;
#pragma unroll
    for (int t = 0; t < 9; t++) s += p[t] * p[t];
    float cs = conv_scale();
    g_Q[idx] = s * cs * cs;
}

__global__ void demod_kernel()
{
    int gw = (blockIdx.x * blockDim.x + threadIdx.x) >> 5;
    int lane = threadIdx.x & 31;
    if (gw >= 2 * BB * C) return;
    int layer = gw / (BB * C);
    int rem = gw % (BB * C);
    int b = rem / C;
    int co = rem % C;
    const float* Q = g_Q + (size_t)layer * C * C + (size_t)co * C;
    const float* s = (layer ? g_s1 : g_s0) + b * C;
    float acc = 0.f;
    for (int ci = lane; ci < C; ci += 32) { float sv = s[ci]; acc += Q[ci] * sv * sv; }
#pragma unroll
    for (int o = 16; o; o >>= 1) acc += __shfl_xor_sync(0xffffffffu, acc, o);
    if (lane == 0) (layer ? g_d1 : g_d0)[b * C + co] = rsqrtf(acc + 1e-8f);
}

__global__ void upsample_scale_kernel(const float* __restrict__ maps)
{
    int idx = blockIdx.x * blockDim.x + threadIdx.x;
    if (idx >= BB * C * H2 * H2) return;
    int x = idx & 63;
    int y = (idx >> 6) & 63;
    int c = (idx >> 12) & (C - 1);
    int b = idx >> 21;
    float sy = 0.5f * y - 0.25f;
    float sx = 0.5f * x - 0.25f;
    int yi = (int)floorf(sy);
    int xi = (int)floorf(sx);
    float wy = sy - yi;
    float wx = sx - xi;
    int ya = yi < 0 ? 0 : yi;
    int yb = yi + 1 > HS - 1 ? HS - 1 : yi + 1;
    int xa = xi < 0 ? 0 : xi;
    int xb = xi + 1 > HS - 1 ? HS - 1 : xi + 1;
    const float* m = maps + ((size_t)b * C + c) * HS * HS;
    float v = (1.f - wy) * ((1.f - wx) * m[ya * HS + xa] + wx * m[ya * HS + xb]) +
              wy * ((1.f - wx) * m[yb * HS + xa] + wx * m[yb * HS + xb]);
    g_x0[idx] = v * g_s0[b * C + c];
}

// ---------------- zero padded-border rows of A slabs --------------
__global__ void zero_pad_kernel()
{
    int i = blockIdx.x * 256 + threadIdx.x;   // 32 slabs * 260 rows * 8 chunks
    if (i >= 32 * 260 * 8) return;
    int ch = i & 7;
    int t = i >> 3;
    int slab = t / 260;
    int rr = t % 260;
    int r;
    if (rr < 66) r = rr;                        // y = -1 band
    else if (rr < 132) r = 4290 + (rr - 66);    // y = 64 band
    else if (rr < 196) r = (rr - 132 + 1) * 66; // x = -1 column
    else r = (rr - 196 + 1) * 66 + 65;          // x = 64 column
    size_t off = ((size_t)slab * SLAB_ROWS + r) * 128 + ch * 16;
    uint4 z = make_uint4(0u, 0u, 0u, 0u);
    *(uint4*)(g_Ah + off) = z;
    *(uint4*)(g_Al + off) = z;
}

// ---------------- prep A: x[b][ci][y][x] -> padded bf16 hi/lo -----
// row r = (y+1)*66 + (x+1); row content = 64 ci bf16 (128 B)
__global__ __launch_bounds__(256)
void prep_A_kernel(const float* __restrict__ x)
{
    __shared__ float tile[64][65];
    const int y = blockIdx.x;     // 0..63
    const int cig = blockIdx.y;   // 0..7
    const int b = blockIdx.z;
    const int tid = threadIdx.x;
    const float* xp = x + ((size_t)(b * C + cig * 64) * 64 + y) * 64;
    for (int i = tid; i < 4096; i += 256)
        tile[i >> 6][i & 63] = xp[(size_t)(i >> 6) * 4096 + (i & 63)];
    __syncthreads();
    const int xo = tid >> 2;      // pixel x
    const int q = tid & 3;        // 16-ci quarter
    uint32_t hh[8], ll[8];
#pragma unroll
    for (int k = 0; k < 8; k++) {
        float v0 = tile[q * 16 + 2 * k][xo];
        float v1 = tile[q * 16 + 2 * k + 1][xo];
        hh[k] = pack_bf16(v0, v1);
        ll[k] = pack_bf16(bf16_lo_res(v0), bf16_lo_res(v1));
    }
    size_t r = (size_t)(y + 1) * 66 + xo + 1;
    size_t base = (((size_t)(b * 8 + cig)) * SLAB_ROWS + r) * 128 + q * 32;
    *(uint4*)(g_Ah + base)      = make_uint4(hh[0], hh[1], hh[2], hh[3]);
    *(uint4*)(g_Ah + base + 16) = make_uint4(hh[4], hh[5], hh[6], hh[7]);
    *(uint4*)(g_Al + base)      = make_uint4(ll[0], ll[1], ll[2], ll[3]);
    *(uint4*)(g_Al + base + 16) = make_uint4(ll[4], ll[5], ll[6], ll[7]);
}

// ---------------- prep B: weights -> bf16 hi/lo [lyr][dy][dx][cig][co][128B]
__global__ void prep_B_kernel(const float* __restrict__ w0, const float* __restrict__ w1)
{
    int idx = blockIdx.x * 256 + threadIdx.x;   // 2*9*8*512*8
    if (idx >= 589824) return;
    int g = idx & 7;
    int t = idx >> 3;
    int co = t & 511; t >>= 9;
    int cig = t & 7; t >>= 3;
    int dx = t % 3; t /= 3;
    int dy = t % 3;
    int layer = t / 3;
    const float* W = layer ? w1 : w0;
    const float cs = conv_scale();
    uint32_t hh[4], ll[4];
#pragma unroll
    for (int k = 0; k < 4; k++) {
        int ci0 = cig * 64 + g * 8 + 2 * k;
        float v0 = W[(((size_t)co * C + ci0) * 3 + dy) * 3 + dx] * cs;
        float v1 = W[(((size_t)co * C + ci0 + 1) * 3 + dy) * 3 + dx] * cs;
        hh[k] = pack_bf16(v0, v1);
        ll[k] = pack_bf16(bf16_lo_res(v0), bf16_lo_res(v1));
    }
    size_t off = ((size_t)(((layer * 3 + dy) * 3 + dx) * 8 + cig) * 512 + co) * 128 + g * 16;
    *(uint4*)(g_Bh + off) = make_uint4(hh[0], hh[1], hh[2], hh[3]);
    *(uint4*)(g_Bl + off) = make_uint4(ll[0], ll[1], ll[2], ll[3]);
}

// ---------------- HMMA conv GEMM ----------------------------------
// CTA 128 px x 256 co, 8 warps (2m x 4n), warp 64x64. 72 merged stages:
// each stage = {Ah,Al,Bh,Bl} for one (dy,dx,cig) K-chunk of 64; 3 passes
// (Ah*Bh, Al*Bh, Ah*Bl) accumulate into one f32 acc. 2-stage cp.async pipe.
__global__ __launch_bounds__(256, 1)
void hgemm_conv_kernel(const unsigned char* __restrict__ Ah, const unsigned char* __restrict__ Al,
                       const unsigned char* __restrict__ Bh, const unsigned char* __restrict__ Bl,
                       const float* __restrict__ dmod, const float* __restrict__ bias,
                       const float* __restrict__ ns, const float* __restrict__ noise,
                       const float* __restrict__ snext, float* __restrict__ out)
{
    extern __shared__ unsigned char sm[];
    const uint32_t sb = smem_u32(sm);
    const int tid = threadIdx.x;
    const int wid = tid >> 5;
    const int lane = tid & 31;
    const int tm = blockIdx.x;    // 0..31 (2 output rows)
    const int nb = blockIdx.y;    // 0..1 (co half)
    const int b = blockIdx.z;
    const int wm = wid >> 2;      // 0..1
    const int wn = wid & 3;       // 0..3

    auto load_stage = [&](int s) {
        int dy = s / 24, r2 = s % 24, dx = r2 / 8, cig = r2 % 8;
        const unsigned char* gAh = Ah + ((size_t)(b * 8 + cig) * SLAB_ROWS) * 128;
        const unsigned char* gAl = Al + ((size_t)(b * 8 + cig) * SLAB_ROWS) * 128;
        const size_t boff = ((size_t)((dy * 3 + dx) * 8 + cig) * 512 + nb * 256) * 128;
        const unsigned char* gBh = Bh + boff;
        const unsigned char* gBl = Bl + boff;
        const int seg0 = (2 * tm + dy) * 66 + dx;
        uint32_t buf = sb + (uint32_t)(s & 1) * STAGE_B;
#pragma unroll
        for (int i = 0; i < 4; i++) {
            int id = tid + i * 256;
            int row = id >> 3, cc = id & 7;
            int grow = seg0 + row + ((row >= 64) ? 2 : 0);
            uint32_t sw = (uint32_t)(cc ^ (row & 7)) << 4;
            CP_ASYNC16(buf + ((uint32_t)row << 7) + sw, gAh + ((size_t)grow << 7) + (cc << 4));
            CP_ASYNC16(buf + 16384u + ((uint32_t)row << 7) + sw, gAl + ((size_t)grow << 7) + (cc << 4));
        }
#pragma unroll
        for (int i = 0; i < 8; i++) {
            int id = tid + i * 256;
            int row = id >> 3, cc = id & 7;
            uint32_t sw = (uint32_t)(cc ^ (row & 7)) << 4;
            CP_ASYNC16(buf + 32768u + ((uint32_t)row << 7) + sw, gBh + ((size_t)id << 4));
            CP_ASYNC16(buf + 65536u + ((uint32_t)row << 7) + sw, gBl + ((size_t)id << 4));
        }
    };

    float acc[4][8][4];
#pragma unroll
    for (int mi = 0; mi < 4; mi++)
#pragma unroll
        for (int nj = 0; nj < 8; nj++)
#pragma unroll
            for (int q = 0; q < 4; q++) acc[mi][nj][q] = 0.f;

    load_stage(0); CP_COMMIT();

#pragma unroll 1
    for (int s = 0; s < NSTAGES; s++) {
        if (s + 1 < NSTAGES) { load_stage(s + 1); CP_COMMIT(); CP_WAIT1(); }
        else CP_WAIT0();
        __syncthreads();
        const uint32_t st = sb + (uint32_t)(s & 1) * STAGE_B;
#pragma unroll
        for (int ks = 0; ks < 4; ks++) {
            const int c = ks * 2 + (lane >> 4);
            uint32_t ah[4][4], al[4][4], bb[4][4];
#pragma unroll
            for (int mi = 0; mi < 4; mi++) {
                int m = wm * 64 + mi * 16 + (lane & 15);
                uint32_t off = ((uint32_t)m << 7) + ((uint32_t)(c ^ (m & 7)) << 4);
                ldsm4(ah[mi], st + off);
                ldsm4(al[mi], st + 16384u + off);
            }
#pragma unroll
            for (int nq = 0; nq < 4; nq++) {
                int n = wn * 64 + nq * 16 + (lane & 15);
                uint32_t off = ((uint32_t)n << 7) + ((uint32_t)(c ^ (n & 7)) << 4);
                ldsm4(bb[nq], st + 32768u + off);
            }
#pragma unroll
            for (int mi = 0; mi < 4; mi++)
#pragma unroll
                for (int nj = 0; nj < 8; nj++)
                    mma_bf16(acc[mi][nj], ah[mi], bb[nj >> 1][nj & 1], bb[nj >> 1][(nj & 1) + 2]);
#pragma unroll
            for (int mi = 0; mi < 4; mi++)
#pragma unroll
                for (int nj = 0; nj < 8; nj++)
                    mma_bf16(acc[mi][nj], al[mi], bb[nj >> 1][nj & 1], bb[nj >> 1][(nj & 1) + 2]);
#pragma unroll
            for (int nq = 0; nq < 4; nq++) {
                int n = wn * 64 + nq * 16 + (lane & 15);
                uint32_t off = ((uint32_t)n << 7) + ((uint32_t)(c ^ (n & 7)) << 4);
                ldsm4(bb[nq], st + 65536u + off);
            }
#pragma unroll
            for (int mi = 0; mi < 4; mi++)
#pragma unroll
                for (int nj = 0; nj < 8; nj++)
                    mma_bf16(acc[mi][nj], ah[mi], bb[nj >> 1][nj & 1], bb[nj >> 1][(nj & 1) + 2]);
        }
        __syncthreads();
    }

    // transpose through smem (reuses stage buffers) -> coalesced stores
    float* T = (float*)sm;   // [256 co][132]
#pragma unroll
    for (int mi = 0; mi < 4; mi++)
#pragma unroll
        for (int nj = 0; nj < 8; nj++) {
            int mrow = wm * 64 + mi * 16 + (lane >> 2);
            int ncol = wn * 64 + nj * 8 + (lane & 3) * 2;
            T[(ncol    ) * 132 + mrow    ] = acc[mi][nj][0];
            T[(ncol + 1) * 132 + mrow    ] = acc[mi][nj][1];
            T[(ncol    ) * 132 + mrow + 8] = acc[mi][nj][2];
            T[(ncol + 1) * 132 + mrow + 8] = acc[mi][nj][3];
        }
    __syncthreads();
    {
        const int co = tid;
        const int cog = nb * 256 + co;
        const float dv = dmod[b * C + cog];
        const float bv = bias[cog];
        const float nv = ns[cog];
        const float sv = snext ? snext[b * C + cog] : 1.f;
#pragma unroll
        for (int half = 0; half < 2; half++) {
            const int y = 2 * tm + half;
            const float* np = noise + ((size_t)b * 64 + y) * 64;
            float* op = out + ((size_t)(b * C + cog) * 64 + y) * 64;
            const float* tr = T + co * 132 + half * 64;
#pragma unroll
            for (int x4 = 0; x4 < 16; x4++) {
                float4 t = *(const float4*)(tr + x4 * 4);
                float4 n4 = *(const float4*)(np + x4 * 4);
                float4 o;
                float v;
                v = t.x * dv + bv + nv * n4.x; v = v >= 0.f ? v : 0.2f * v; o.x = v * sv;
                v = t.y * dv + bv + nv * n4.y; v = v >= 0.f ? v : 0.2f * v; o.y = v * sv;
                v = t.z * dv + bv + nv * n4.z; v = v >= 0.f ? v : 0.2f * v; o.z = v * sv;
                v = t.w * dv + bv + nv * n4.w; v = v >= 0.f ? v : 0.2f * v; o.w = v * sv;
                *(float4*)(op + x4 * 4) = o;
            }
        }
    }
}

// ---------------- to_rgb ------------------------------------------
__global__ void rgb_kernel(const float* __restrict__ rgb_in, const float* __restrict__ rgb_w,
                           const float* __restrict__ rgb_b, const float* __restrict__ h,
                           float* __restrict__ out)
{
    __shared__ float coef[3 * C];
    __shared__ float part[4][3][64];
    int b = blockIdx.x >> 6;
    int y = blockIdx.x & 63;
    int tid = threadIdx.x;
    const float rs = rgb_scale();
    for (int i = tid; i < 3 * C; i += 256) {
        int c2 = i >> 9;
        int co = i & (C - 1);
        coef[i] = rgb_w[c2 * C + co] * rs * g_sr[b * C + co];
    }
    __syncthreads();
    int px = tid & 63;
    int cg = tid >> 6;
    float a0 = 0.f, a1 = 0.f, a2 = 0.f;
    const float* hp = h + (((size_t)b * C + cg * 128) * 64 + y) * 64 + px;
    const float* c0 = coef + cg * 128;
    for (int co = 0; co < 128; co++) {
        float hv = hp[(size_t)co * 4096];
        a0 += c0[co] * hv;
        a1 += c0[C + co] * hv;
        a2 += c0[2 * C + co] * hv;
    }
    part[cg][0][px] = a0;
    part[cg][1][px] = a1;
    part[cg][2][px] = a2;
    __syncthreads();
    if (tid < 192) {
        int c2 = tid / 64;
        int x = tid % 64;
        float s = part[0][c2][x] + part[1][c2][x] + part[2][c2][x] + part[3][c2][x];
        float sy = 0.5f * y - 0.25f;
        float sx = 0.5f * x - 0.25f;
        int yi = (int)floorf(sy);
        int xi = (int)floorf(sx);
        float wy = sy - yi;
        float wx = sx - xi;
        int ya = yi < 0 ? 0 : yi;
        int yb = yi + 1 > HS - 1 ? HS - 1 : yi + 1;
        int xa = xi < 0 ? 0 : xi;
        int xb2 = xi + 1 > HS - 1 ? HS - 1 : xi + 1;
        const float* rp = rgb_in + ((size_t)b * 3 + c2) * HS * HS;
        float up = (1.f - wy) * ((1.f - wx) * rp[ya * HS + xa] + wx * rp[ya * HS + xb2]) +
                   wy * ((1.f - wx) * rp[yb * HS + xa] + wx * rp[yb * HS + xb2]);
        out[(((size_t)b * 3 + c2) * 64 + y) * 64 + x] = up + rgb_b[c2] + s;
    }
}

// ---------------- launch ------------------------------------------
extern "C" void kernel_launch(void* const* d_in, const int* in_sizes, int n_in,
                              void* d_out, int out_size)
{
    const float* maps    = (const float*)d_in[0];
    const float* w       = (const float*)d_in[1];
    const float* rgb     = (const float*)d_in[2];
    const float* noise0  = (const float*)d_in[3];
    const float* noise1  = (const float*)d_in[4];
    const float* conv0_w = (const float*)d_in[5];
    const float* conv0_b = (const float*)d_in[6];
    const float* ms0_w   = (const float*)d_in[7];
    const float* ms0_b   = (const float*)d_in[8];
    const float* ns0     = (const float*)d_in[9];
    const float* conv1_w = (const float*)d_in[10];
    const float* conv1_b = (const float*)d_in[11];
    const float* ms1_w   = (const float*)d_in[12];
    const float* ms1_b   = (const float*)d_in[13];
    const float* ns1     = (const float*)d_in[14];
    const float* rgb_w   = (const float*)d_in[15];
    const float* rgb_b   = (const float*)d_in[16];
    const float* msr_w   = (const float*)d_in[17];
    const float* msr_b   = (const float*)d_in[18];

    float* out = (float*)d_out;
    float* out_rgb = out;
    float* out_h   = out + 4 * 3 * 64 * 64;

    float *px0, *px1, *pd0, *pd1, *ps1;
    unsigned char *pAh, *pAl, *pBh, *pBl;
    cudaGetSymbolAddress((void**)&px0, g_x0);
    cudaGetSymbolAddress((void**)&px1, g_x1);
    cudaGetSymbolAddress((void**)&pd0, g_d0);
    cudaGetSymbolAddress((void**)&pd1, g_d1);
    cudaGetSymbolAddress((void**)&ps1, g_s1);
    cudaGetSymbolAddress((void**)&pAh, g_Ah);
    cudaGetSymbolAddress((void**)&pAl, g_Al);
    cudaGetSymbolAddress((void**)&pBh, g_Bh);
    cudaGetSymbolAddress((void**)&pBl, g_Bl);

    cudaFuncSetAttribute(hgemm_conv_kernel,
                         cudaFuncAttributeMaxDynamicSharedMemorySize, SM_GEMM);

    styles_kernel<<<768, 256>>>(w, ms0_w, ms0_b, ms1_w, ms1_b, msr_w, msr_b);
    q_kernel<<<(2 * C * C + 255) / 256, 256>>>(conv0_w, conv1_w);
    demod_kernel<<<(2 * BB * C * 32 + 255) / 256, 256>>>();
    upsample_scale_kernel<<<(BB * C * H2 * H2) / 256, 256>>>(maps);
    prep_B_kernel<<<2304, 256>>>(conv0_w, conv1_w);
    zero_pad_kernel<<<260, 256>>>();

    prep_A_kernel<<<dim3(64, 8, BB), 256>>>(px0);
    hgemm_conv_kernel<<<dim3(32, 2, BB), 256, SM_GEMM>>>(
        pAh, pAl, pBh, pBl, pd0, conv0_b, ns0, noise0, ps1, px1);

    prep_A_kernel<<<dim3(64, 8, BB), 256>>>(px1);
    hgemm_conv_kernel<<<dim3(32, 2, BB), 256, SM_GEMM>>>(
        pAh, pAl, pBh + B_LAYER_OFF, pBl + B_LAYER_OFF, pd1, conv1_b, ns1, noise1,
        nullptr, out_h);

    rgb_kernel<<<BB * 64, 256>>>(rgb, rgb_w, rgb_b, out_h, out_rgb);
}